// round 11
// baseline (speedup 1.0000x reference)
#include <cuda_runtime.h>
#include <cuda_bf16.h>

#define ALPHA_MARGIN 1.0f

__device__ __forceinline__ void do_pair(
    float4 a, float4 b, const int* __restrict__ y,
    float* __restrict__ out, int p, int lane)
{
    float dx = a.x - b.x, dy = a.y - b.y;
    float dz = a.z - b.z, dw = a.w - b.w;
    float s = dx * dx + dy * dy + dz * dz + dw * dw;
    #pragma unroll
    for (int o = 16; o > 0; o >>= 1)
        s += __shfl_xor_sync(0xffffffffu, s, o);
    if (lane == 0) {
        int adj = y[p];
        out[p] = (adj == 1) ? s
               : (adj == 0) ? fmaxf(ALPHA_MARGIN - s, 0.0f)
               : 0.0f;
    }
}

// Specialized kernel: assumes n_pairs % (nwarps*2) == 0, so the hot loop has
// no bounds predicates — straight-line 4x LDG.128 batch per iteration.
__global__ __launch_bounds__(256) void contrastive_loss_exact(
    const float* __restrict__ X,
    const int*   __restrict__ y,
    float*       __restrict__ out,
    int n_pairs)
{
    const int lane   = threadIdx.x & 31;
    const int gwarp  = (blockIdx.x * blockDim.x + threadIdx.x) >> 5;
    const int nwarps = (gridDim.x * blockDim.x) >> 5;
    const int stride = nwarps * 2;
    const int iters  = n_pairs / stride;   // exact

    const float4* Xv = reinterpret_cast<const float4*>(X);
    int p = gwarp * 2;

    const float4* r = Xv + (size_t)p * 64;
    float4 a0 = __ldg(r + lane);
    float4 b0 = __ldg(r + 32 + lane);
    float4 a1 = __ldg(r + 64 + lane);
    float4 b1 = __ldg(r + 96 + lane);

    for (int it = 0; it < iters - 1; it++) {
        const int pn = p + stride;

        // Unconditional prefetch of next iteration (front-batched LDG.128 x4)
        const float4* rn = Xv + (size_t)pn * 64;
        float4 na0 = __ldg(rn + lane);
        float4 nb0 = __ldg(rn + 32 + lane);
        float4 na1 = __ldg(rn + 64 + lane);
        float4 nb1 = __ldg(rn + 96 + lane);

        do_pair(a0, b0, y, out, p,     lane);
        do_pair(a1, b1, y, out, p + 1, lane);

        a0 = na0; b0 = nb0; a1 = na1; b1 = nb1;
        p = pn;
    }
    // Epilogue iteration (no prefetch)
    do_pair(a0, b0, y, out, p,     lane);
    do_pair(a1, b1, y, out, p + 1, lane);
}

// Generic fallback (guarded), correct for any n_pairs.
__global__ __launch_bounds__(256) void contrastive_loss_generic(
    const float* __restrict__ X,
    const int*   __restrict__ y,
    float*       __restrict__ out,
    int n_pairs)
{
    const int lane   = threadIdx.x & 31;
    const int gwarp  = (blockIdx.x * blockDim.x + threadIdx.x) >> 5;
    const int nwarps = (gridDim.x * blockDim.x) >> 5;

    const float4* Xv = reinterpret_cast<const float4*>(X);
    for (int p = gwarp; p < n_pairs; p += nwarps) {
        const float4* r = Xv + (size_t)p * 64;
        float4 a = __ldg(r + lane);
        float4 b = __ldg(r + 32 + lane);
        do_pair(a, b, y, out, p, lane);
    }
}

extern "C" void kernel_launch(void* const* d_in, const int* in_sizes, int n_in,
                              void* d_out, int out_size)
{
    const float* X = (const float*)d_in[0];
    const int*   y = (const int*)d_in[1];
    float*       out = (float*)d_out;

    int n_pairs = out_size;              // B*N*N = 524288
    int blocks  = 2048;
    int stride  = (blocks * 256 / 32) * 2;   // 32768

    if (n_pairs % stride == 0) {
        contrastive_loss_exact<<<blocks, 256>>>(X, y, out, n_pairs);
    } else {
        contrastive_loss_generic<<<blocks, 256>>>(X, y, out, n_pairs);
    }
}

// round 12
// speedup vs baseline: 1.0287x; 1.0287x over previous
#include <cuda_runtime.h>
#include <cuda_bf16.h>

#define ALPHA_MARGIN 1.0f

// FINAL KERNEL (best-measured config, reproduced twice: 80.38us R2, 80.64us R10).
// Persistent grid-stride kernel: each warp processes 2 pairs per iteration
// (4 x LDG.128 per lane, fully coalesced 512B chunks), with the next
// iteration's loads prefetched before the current reduction so ~8 LDG.128
// stay in flight through the SHFL chain.
//
// This problem is HBM-streaming-bound: 541MB compulsory traffic at the chip's
// ~6.8TB/s effective streaming ceiling = ~79-80us floor. 11 rounds of
// alternatives (deeper MLP, resident grids, cache hints, epilogue fusion,
// predicate removal) all measured neutral or worse — this shape is at the
// hardware ceiling.
__global__ __launch_bounds__(256) void contrastive_loss_kernel(
    const float* __restrict__ X,
    const int*   __restrict__ y,
    float*       __restrict__ out,
    int n_pairs)
{
    const int lane   = threadIdx.x & 31;
    const int gwarp  = (blockIdx.x * blockDim.x + threadIdx.x) >> 5;
    const int nwarps = (gridDim.x * blockDim.x) >> 5;
    const int stride = nwarps * 2;

    const float4* Xv = reinterpret_cast<const float4*>(X);
    int p = gwarp * 2;

    float4 a0, b0, a1, b1;
    if (p < n_pairs) {
        const float4* r0 = Xv + (size_t)p * 64;
        a0 = __ldg(r0 + lane);
        b0 = __ldg(r0 + 32 + lane);
    }
    if (p + 1 < n_pairs) {
        const float4* r1 = Xv + (size_t)(p + 1) * 64;
        a1 = __ldg(r1 + lane);
        b1 = __ldg(r1 + 32 + lane);
    }

    while (p < n_pairs) {
        const int pn = p + stride;

        // Prefetch next iteration before reducing current
        float4 na0, nb0, na1, nb1;
        if (pn < n_pairs) {
            const float4* r0 = Xv + (size_t)pn * 64;
            na0 = __ldg(r0 + lane);
            nb0 = __ldg(r0 + 32 + lane);
        }
        if (pn + 1 < n_pairs) {
            const float4* r1 = Xv + (size_t)(pn + 1) * 64;
            na1 = __ldg(r1 + lane);
            nb1 = __ldg(r1 + 32 + lane);
        }

        // Pair p
        {
            float dx = a0.x - b0.x, dy = a0.y - b0.y;
            float dz = a0.z - b0.z, dw = a0.w - b0.w;
            float s = dx * dx + dy * dy + dz * dz + dw * dw;
            #pragma unroll
            for (int o = 16; o > 0; o >>= 1)
                s += __shfl_xor_sync(0xffffffffu, s, o);
            if (lane == 0) {
                int adj = y[p];
                out[p] = (adj == 1) ? s
                       : (adj == 0) ? fmaxf(ALPHA_MARGIN - s, 0.0f)
                       : 0.0f;
            }
        }

        // Pair p+1
        if (p + 1 < n_pairs) {
            float dx = a1.x - b1.x, dy = a1.y - b1.y;
            float dz = a1.z - b1.z, dw = a1.w - b1.w;
            float s = dx * dx + dy * dy + dz * dz + dw * dw;
            #pragma unroll
            for (int o = 16; o > 0; o >>= 1)
                s += __shfl_xor_sync(0xffffffffu, s, o);
            if (lane == 0) {
                int adj = y[p + 1];
                out[p + 1] = (adj == 1) ? s
                           : (adj == 0) ? fmaxf(ALPHA_MARGIN - s, 0.0f)
                           : 0.0f;
            }
        }

        a0 = na0; b0 = nb0; a1 = na1; b1 = nb1;
        p = pn;
    }
}

extern "C" void kernel_launch(void* const* d_in, const int* in_sizes, int n_in,
                              void* d_out, int out_size)
{
    const float* X = (const float*)d_in[0];
    const int*   y = (const int*)d_in[1];
    float*       out = (float*)d_out;

    int n_pairs = out_size;      // B*N*N = 524288
    int blocks  = 2048;          // best-measured shape
    contrastive_loss_kernel<<<blocks, 256>>>(X, y, out, n_pairs);
}